// round 2
// baseline (speedup 1.0000x reference)
#include <cuda_runtime.h>
#include <cstdint>

// ---------------- problem constants (fixed by this input set) ----------------
#define BATCH    8
#define NPTS     8192
#define NTOT     65536
#define NPOINT   512
#define NSAMPLE  32
#define CIN      64
#define R2       (0.1f * 0.1f)

// d_out packing (float32), tuple flattened in return order:
#define OFF_XYZ   0                                   // new_xyz  [8,512,3]
#define OFF_IDX   (BATCH * NPOINT * 3)                // new_idx  [8,512]
#define OFF_FEAT  (OFF_IDX + BATCH * NPOINT)          // new_feat [8,128,512]
#define OFF_SIDS  (OFF_FEAT + BATCH * 128 * NPOINT)   // sample_ids [8,512,32]

// ---------------- scratch (device globals; no runtime allocation) ------------
__device__ int   g_new_idx[BATCH * NPOINT];
__device__ float g_new_xyz[BATCH * NPOINT * 3];
__device__ int   g_sample_ids[BATCH * NPOINT * NSAMPLE];
__device__ float g_featT[(size_t)NTOT * CIN];   // [n][c] transposed features

// =============================================================================
// 1) Furthest point sampling: 1 block per batch, 1024 threads, 8 pts/thread.
//    Exact-match arithmetic: non-contracted (dx*dx + dy*dy) + dz*dz.
//    Argmax tie-break = lowest index, via key = (dist_bits<<32) | ~idx.
// =============================================================================
extern __shared__ float dyn_smem[];

__global__ void __launch_bounds__(1024) fps_kernel(const float* __restrict__ xyz,
                                                   float* __restrict__ out) {
    float* spx = dyn_smem;
    float* spy = spx + NPTS;
    float* spz = spy + NPTS;
    __shared__ unsigned long long red[32];
    __shared__ float lastp[3];

    const int b = blockIdx.x;
    const int t = threadIdx.x;
    const float* src = xyz + (size_t)b * NPTS * 3;

    // load 8 consecutive points (24 floats = 6 float4) into registers
    float f[24];
    {
        const float4* s4 = (const float4*)src;
        float4* f4 = (float4*)f;
#pragma unroll
        for (int i = 0; i < 6; i++) f4[i] = s4[t * 6 + i];
    }
    float px[8], py[8], pz[8], dd[8];
#pragma unroll
    for (int j = 0; j < 8; j++) {
        px[j] = f[3 * j + 0];
        py[j] = f[3 * j + 1];
        pz[j] = f[3 * j + 2];
        dd[j] = 1e10f;
        spx[t * 8 + j] = px[j];
        spy[t * 8 + j] = py[j];
        spz[t * 8 + j] = pz[j];
    }
    if (t == 0) {
        lastp[0] = px[0]; lastp[1] = py[0]; lastp[2] = pz[0];
        g_new_idx[b * NPOINT] = 0;
        g_new_xyz[(size_t)(b * NPOINT) * 3 + 0] = px[0];
        g_new_xyz[(size_t)(b * NPOINT) * 3 + 1] = py[0];
        g_new_xyz[(size_t)(b * NPOINT) * 3 + 2] = pz[0];
        out[OFF_IDX + b * NPOINT] = 0.0f;
        out[OFF_XYZ + (size_t)(b * NPOINT) * 3 + 0] = px[0];
        out[OFF_XYZ + (size_t)(b * NPOINT) * 3 + 1] = py[0];
        out[OFF_XYZ + (size_t)(b * NPOINT) * 3 + 2] = pz[0];
    }
    __syncthreads();

    const int wid = t >> 5, lane = t & 31;

    for (int it = 1; it < NPOINT; ++it) {
        const float lx = lastp[0], ly = lastp[1], lz = lastp[2];
        unsigned long long best = 0ull;
#pragma unroll
        for (int j = 0; j < 8; j++) {
            float dx = __fsub_rn(px[j], lx);
            float dy = __fsub_rn(py[j], ly);
            float dz = __fsub_rn(pz[j], lz);
            float d2 = __fadd_rn(__fadd_rn(__fmul_rn(dx, dx), __fmul_rn(dy, dy)),
                                 __fmul_rn(dz, dz));
            dd[j] = fminf(dd[j], d2);
            unsigned long long key =
                ((unsigned long long)__float_as_uint(dd[j]) << 32) |
                (unsigned)(~(unsigned)(t * 8 + j));
            best = (key > best) ? key : best;
        }
#pragma unroll
        for (int off = 16; off; off >>= 1) {
            unsigned long long o = __shfl_down_sync(0xffffffffu, best, off);
            if (o > best) best = o;
        }
        if (lane == 0) red[wid] = best;
        __syncthreads();
        if (wid == 0) {
            unsigned long long v = red[lane];
#pragma unroll
            for (int off = 16; off; off >>= 1) {
                unsigned long long o = __shfl_down_sync(0xffffffffu, v, off);
                if (o > v) v = o;
            }
            if (lane == 0) {
                int idx = (int)(~(unsigned)v);
                float x = spx[idx], y = spy[idx], z = spz[idx];
                lastp[0] = x; lastp[1] = y; lastp[2] = z;
                g_new_idx[b * NPOINT + it] = idx;
                g_new_xyz[(size_t)(b * NPOINT + it) * 3 + 0] = x;
                g_new_xyz[(size_t)(b * NPOINT + it) * 3 + 1] = y;
                g_new_xyz[(size_t)(b * NPOINT + it) * 3 + 2] = z;
                out[OFF_IDX + b * NPOINT + it] = (float)idx;
                out[OFF_XYZ + (size_t)(b * NPOINT + it) * 3 + 0] = x;
                out[OFF_XYZ + (size_t)(b * NPOINT + it) * 3 + 1] = y;
                out[OFF_XYZ + (size_t)(b * NPOINT + it) * 3 + 2] = z;
            }
        }
        __syncthreads();
    }
}

// =============================================================================
// 2) Feature transpose [64, 65536] -> [65536, 64]
// =============================================================================
__global__ void transpose_kernel(const float* __restrict__ f) {
    __shared__ float tile[32][33];
    const int n0 = blockIdx.x * 32;
    const int c0 = blockIdx.y * 32;
    const int tx = threadIdx.x, ty = threadIdx.y;
#pragma unroll
    for (int i = 0; i < 4; i++)
        tile[ty + 8 * i][tx] = f[(size_t)(c0 + ty + 8 * i) * NTOT + (n0 + tx)];
    __syncthreads();
#pragma unroll
    for (int i = 0; i < 4; i++)
        g_featT[(size_t)(n0 + ty + 8 * i) * CIN + (c0 + tx)] = tile[tx][ty + 8 * i];
}

// =============================================================================
// 3) Ball query: one warp per center, first NSAMPLE in-ball points in index
//    order, pad with first in-ball index (pointnet2 semantics).
// =============================================================================
__global__ void __launch_bounds__(256) ballq_kernel(const float* __restrict__ xyz,
                                                    float* __restrict__ out) {
    float* spx = dyn_smem;
    float* spy = spx + NPTS;
    float* spz = spy + NPTS;
    __shared__ int sm_ids[8][NSAMPLE];

    const int b = blockIdx.x >> 6;
    const int cblk = blockIdx.x & 63;
    const float* src = xyz + (size_t)b * NPTS * 3;

    for (int i = threadIdx.x; i < NPTS; i += 256) {
        spx[i] = src[3 * i + 0];
        spy[i] = src[3 * i + 1];
        spz[i] = src[3 * i + 2];
    }
    __syncthreads();

    const int w = threadIdx.x >> 5, lane = threadIdx.x & 31;
    const int gc = b * NPOINT + cblk * 8 + w;
    const float cx = g_new_xyz[(size_t)gc * 3 + 0];
    const float cy = g_new_xyz[(size_t)gc * 3 + 1];
    const float cz = g_new_xyz[(size_t)gc * 3 + 2];

    int count = 0, first = -1;
    for (int chunk = 0; chunk < NPTS / 32; ++chunk) {
        const int p = chunk * 32 + lane;
        float dx = __fsub_rn(cx, spx[p]);
        float dy = __fsub_rn(cy, spy[p]);
        float dz = __fsub_rn(cz, spz[p]);
        float d2 = __fadd_rn(__fadd_rn(__fmul_rn(dx, dx), __fmul_rn(dy, dy)),
                             __fmul_rn(dz, dz));
        const bool in = d2 < R2;
        const unsigned m = __ballot_sync(0xffffffffu, in);
        if (m) {
            if (first < 0) first = chunk * 32 + __ffs(m) - 1;
            if (in) {
                int rank = count + __popc(m & ((1u << lane) - 1u));
                if (rank < NSAMPLE) sm_ids[w][rank] = p;
            }
            count += __popc(m);
            if (count >= NSAMPLE) break;
        }
    }
    __syncwarp();
    if (first < 0) first = 0;
    const int id = (lane < count) ? sm_ids[w][lane] : first;
    g_sample_ids[(size_t)gc * NSAMPLE + lane] = id;
    out[OFF_SIDS + (size_t)gc * NSAMPLE + lane] = (float)id;
}

// =============================================================================
// 4) Fused gather + MLP(67->64->64->128, ReLU each) + max over samples.
//    One block = 8 centers = 256 sample columns. Register-tiled 8x8 GEMMs.
// =============================================================================
template <int K, int LDA>
__device__ __forceinline__ void gemm8x8(const float* __restrict__ A,
                                        const float* __restrict__ Bm,
                                        int o0, int s0, float acc[8][8]) {
#pragma unroll
    for (int i = 0; i < 8; i++)
#pragma unroll
        for (int j = 0; j < 8; j++) acc[i][j] = 0.0f;
#pragma unroll 4
    for (int k = 0; k < K; k++) {
        float a[8], bv[8];
        *(float4*)&a[0] = *(const float4*)&A[k * LDA + o0];
        *(float4*)&a[4] = *(const float4*)&A[k * LDA + o0 + 4];
        *(float4*)&bv[0] = *(const float4*)&Bm[k * 256 + s0];
        *(float4*)&bv[4] = *(const float4*)&Bm[k * 256 + s0 + 4];
#pragma unroll
        for (int i = 0; i < 8; i++)
#pragma unroll
            for (int j = 0; j < 8; j++) acc[i][j] += a[i] * bv[j];
    }
}

__global__ void __launch_bounds__(256) mlp_kernel(const float* __restrict__ xyz,
                                                  const float* __restrict__ W0,
                                                  const float* __restrict__ b0,
                                                  const float* __restrict__ W1,
                                                  const float* __restrict__ b1,
                                                  const float* __restrict__ W2,
                                                  const float* __restrict__ b2,
                                                  float* __restrict__ out) {
    float* sW0 = dyn_smem;          // [67][64]  (k-major)
    float* sb0 = sW0 + 67 * 64;
    float* sW1 = sb0 + 64;          // [64][64]
    float* sb1 = sW1 + 64 * 64;
    float* sW2 = sb1 + 64;          // [64][128]
    float* sb2 = sW2 + 64 * 128;
    float* X0  = sb2 + 128;         // [67][256]  (also reused as H2 [64][256])
    float* H1  = X0 + 67 * 256;     // [64][256]

    const int tid = threadIdx.x;
    const int b = blockIdx.x >> 6;
    const int cgrp = blockIdx.x & 63;

    // stage weights (transposed to k-major) + biases
    for (int i = tid; i < 67 * 64; i += 256) { int k = i >> 6, o = i & 63;  sW0[i] = W0[o * 67 + k]; }
    for (int i = tid; i < 64 * 64; i += 256) { int k = i >> 6, o = i & 63;  sW1[i] = W1[o * 64 + k]; }
    for (int i = tid; i < 64 * 128; i += 256){ int k = i >> 7, o = i & 127; sW2[i] = W2[o * 64 + k]; }
    if (tid < 64)  { sb0[tid] = b0[tid]; sb1[tid] = b1[tid]; }
    if (tid < 128) { sb2[tid] = b2[tid]; }

    // gather: each thread owns one sample column
    {
        const int s = tid;
        const int cl = s >> 5;
        const int gc = b * NPOINT + cgrp * 8 + cl;
        const int pid = g_sample_ids[(size_t)gc * NSAMPLE + (s & 31)];
        const float* p = xyz + ((size_t)b * NPTS + pid) * 3;
        const float cx = g_new_xyz[(size_t)gc * 3 + 0];
        const float cy = g_new_xyz[(size_t)gc * 3 + 1];
        const float cz = g_new_xyz[(size_t)gc * 3 + 2];
        X0[0 * 256 + s] = p[0] - cx;
        X0[1 * 256 + s] = p[1] - cy;
        X0[2 * 256 + s] = p[2] - cz;
        const float4* fp = (const float4*)(g_featT + ((size_t)b * NPTS + pid) * CIN);
#pragma unroll
        for (int q = 0; q < 16; q++) {
            float4 v = fp[q];
            X0[(3 + 4 * q + 0) * 256 + s] = v.x;
            X0[(3 + 4 * q + 1) * 256 + s] = v.y;
            X0[(3 + 4 * q + 2) * 256 + s] = v.z;
            X0[(3 + 4 * q + 3) * 256 + s] = v.w;
        }
    }
    __syncthreads();

    const int ot = tid >> 5, st = tid & 31;
    const int o0 = ot * 8, s0 = st * 8;
    float acc[8][8];

    // layer 1: 67 -> 64
    gemm8x8<67, 64>(sW0, X0, o0, s0, acc);
#pragma unroll
    for (int i = 0; i < 8; i++) {
        const float bi = sb0[o0 + i];
        float* dst = &H1[(o0 + i) * 256 + s0];
#pragma unroll
        for (int j = 0; j < 8; j++) dst[j] = fmaxf(acc[i][j] + bi, 0.0f);
    }
    __syncthreads();

    // layer 2: 64 -> 64  (write H2 into X0 buffer)
    gemm8x8<64, 64>(sW1, H1, o0, s0, acc);
#pragma unroll
    for (int i = 0; i < 8; i++) {
        const float bi = sb1[o0 + i];
        float* dst = &X0[(o0 + i) * 256 + s0];
#pragma unroll
        for (int j = 0; j < 8; j++) dst[j] = fmaxf(acc[i][j] + bi, 0.0f);
    }
    __syncthreads();

    // layer 3: 64 -> 128 in two halves, max-over-samples fused in epilogue
#pragma unroll
    for (int half = 0; half < 2; ++half) {
        gemm8x8<64, 128>(sW2 + half * 64, X0, o0, s0, acc);
#pragma unroll
        for (int i = 0; i < 8; i++) {
            const float bi = sb2[half * 64 + o0 + i];
            float m = 0.0f;  // ReLU outputs are >= 0
#pragma unroll
            for (int j = 0; j < 8; j++) m = fmaxf(m, fmaxf(acc[i][j] + bi, 0.0f));
            m = fmaxf(m, __shfl_xor_sync(0xffffffffu, m, 1));
            m = fmaxf(m, __shfl_xor_sync(0xffffffffu, m, 2));
            if ((st & 3) == 0) {
                const int c = cgrp * 8 + (st >> 2);
                const int o = half * 64 + o0 + i;
                out[OFF_FEAT + ((size_t)b * 128 + o) * NPOINT + c] = m;
            }
        }
    }
}

// =============================================================================
extern "C" void kernel_launch(void* const* d_in, const int* in_sizes, int n_in,
                              void* d_out, int out_size) {
    const float* xyz  = (const float*)d_in[0];
    const float* feat = (const float*)d_in[1];
    const float* W0   = (const float*)d_in[3];
    const float* b0   = (const float*)d_in[4];
    const float* W1   = (const float*)d_in[5];
    const float* b1   = (const float*)d_in[6];
    const float* W2   = (const float*)d_in[7];
    const float* b2   = (const float*)d_in[8];
    float* out = (float*)d_out;

    const int smem_pts = 3 * NPTS * sizeof(float);                 // 98304
    const int smem_mlp = (67*64 + 64 + 64*64 + 64 + 64*128 + 128
                          + 67*256 + 64*256) * sizeof(float);      // 201472

    cudaFuncSetAttribute(fps_kernel,   cudaFuncAttributeMaxDynamicSharedMemorySize, smem_pts);
    cudaFuncSetAttribute(ballq_kernel, cudaFuncAttributeMaxDynamicSharedMemorySize, smem_pts);
    cudaFuncSetAttribute(mlp_kernel,   cudaFuncAttributeMaxDynamicSharedMemorySize, smem_mlp);

    fps_kernel<<<BATCH, 1024, smem_pts>>>(xyz, out);
    transpose_kernel<<<dim3(NTOT / 32, CIN / 32), dim3(32, 8)>>>(feat);
    ballq_kernel<<<BATCH * (NPOINT / 8), 256, smem_pts>>>(xyz, out);
    mlp_kernel<<<BATCH * (NPOINT / 8), 256, smem_mlp>>>(xyz, W0, b0, W1, b1, W2, b2, out);
}

// round 3
// speedup vs baseline: 1.0915x; 1.0915x over previous
#include <cuda_runtime.h>
#include <cstdint>

// ---------------- problem constants (fixed by this input set) ----------------
#define BATCH    8
#define NPTS     8192
#define NTOT     65536
#define NPOINT   512
#define NSAMPLE  32
#define CIN      64
#define R2       (0.1f * 0.1f)

// d_out packing (float32), tuple flattened in return order:
#define OFF_XYZ   0                                   // new_xyz  [8,512,3]
#define OFF_IDX   (BATCH * NPOINT * 3)                // new_idx  [8,512]
#define OFF_FEAT  (OFF_IDX + BATCH * NPOINT)          // new_feat [8,128,512]
#define OFF_SIDS  (OFF_FEAT + BATCH * 128 * NPOINT)   // sample_ids [8,512,32]

// ---------------- scratch (device globals; no runtime allocation) ------------
__device__ int   g_new_idx[BATCH * NPOINT];
__device__ float g_new_xyz[BATCH * NPOINT * 3];
__device__ int   g_sample_ids[BATCH * NPOINT * NSAMPLE];
__device__ float g_featT[(size_t)NTOT * CIN];   // [n][c] transposed features

// ---------------- packed f32x2 helpers (bit-exact per-lane fp32) -------------
__device__ __forceinline__ unsigned long long f2_add(unsigned long long a, unsigned long long b) {
    unsigned long long r;
    asm("add.rn.f32x2 %0, %1, %2;" : "=l"(r) : "l"(a), "l"(b));
    return r;
}
__device__ __forceinline__ unsigned long long f2_mul(unsigned long long a, unsigned long long b) {
    unsigned long long r;
    asm("mul.rn.f32x2 %0, %1, %2;" : "=l"(r) : "l"(a), "l"(b));
    return r;
}
__device__ __forceinline__ unsigned long long f2_pack(float lo, float hi) {
    unsigned long long r;
    asm("mov.b64 %0, {%1, %2};" : "=l"(r) : "f"(lo), "f"(hi));
    return r;
}
__device__ __forceinline__ void f2_unpack(unsigned long long v, float& lo, float& hi) {
    asm("mov.b64 {%0, %1}, %2;" : "=f"(lo), "=f"(hi) : "l"(v));
}

extern __shared__ float dyn_smem[];

// =============================================================================
// 1) Furthest point sampling: 1 block per batch, 1024 threads, 8 pts/thread.
//    Exact-match arithmetic via packed f32x2 add/mul (dx*dx + dy*dy) + dz*dz.
//    Single __syncthreads per iteration: all warps redundantly reduce the 32
//    per-warp bests (double-buffered smem slot) and look up the winner coords.
// =============================================================================
__global__ void __launch_bounds__(1024) fps_kernel(const float* __restrict__ xyz,
                                                   float* __restrict__ out) {
    float* spx = dyn_smem;
    float* spy = spx + NPTS;
    float* spz = spy + NPTS;
    __shared__ unsigned long long red[2][32];

    const int b = blockIdx.x;
    const int t = threadIdx.x;
    const float* src = xyz + (size_t)b * NPTS * 3;

    // load 8 consecutive points (24 floats = 6 float4)
    float f[24];
    {
        const float4* s4 = (const float4*)src;
        float4* f4 = (float4*)f;
#pragma unroll
        for (int i = 0; i < 6; i++) f4[i] = s4[t * 6 + i];
    }
    // pack point pairs: pair a = points (2a, 2a+1)
    unsigned long long pxp[4], pyp[4], pzp[4];
    float dd[8];
#pragma unroll
    for (int a = 0; a < 4; a++) {
        pxp[a] = f2_pack(f[6 * a + 0], f[6 * a + 3]);
        pyp[a] = f2_pack(f[6 * a + 1], f[6 * a + 4]);
        pzp[a] = f2_pack(f[6 * a + 2], f[6 * a + 5]);
    }
#pragma unroll
    for (int j = 0; j < 8; j++) {
        dd[j] = 1e10f;
        spx[t * 8 + j] = f[3 * j + 0];
        spy[t * 8 + j] = f[3 * j + 1];
        spz[t * 8 + j] = f[3 * j + 2];
    }
    if (t == 0) {
        g_new_idx[b * NPOINT] = 0;
        g_new_xyz[(size_t)(b * NPOINT) * 3 + 0] = f[0];
        g_new_xyz[(size_t)(b * NPOINT) * 3 + 1] = f[1];
        g_new_xyz[(size_t)(b * NPOINT) * 3 + 2] = f[2];
        out[OFF_IDX + b * NPOINT] = 0.0f;
        out[OFF_XYZ + (size_t)(b * NPOINT) * 3 + 0] = f[0];
        out[OFF_XYZ + (size_t)(b * NPOINT) * 3 + 1] = f[1];
        out[OFF_XYZ + (size_t)(b * NPOINT) * 3 + 2] = f[2];
    }
    __syncthreads();

    // negated last-point coords, packed (x - l == x + (-l), exact)
    float lx0 = spx[0], ly0 = spy[0], lz0 = spz[0];
    unsigned long long nlx = f2_pack(-lx0, -lx0);
    unsigned long long nly = f2_pack(-ly0, -ly0);
    unsigned long long nlz = f2_pack(-lz0, -lz0);

    const int lane = t & 31, wid = t >> 5;
    const int base = t * 8;

    for (int it = 1; it < NPOINT; ++it) {
        float m = -1.0f;
        int mi = 0;
#pragma unroll
        for (int a = 0; a < 4; a++) {
            unsigned long long dx = f2_add(pxp[a], nlx);
            unsigned long long dy = f2_add(pyp[a], nly);
            unsigned long long dz = f2_add(pzp[a], nlz);
            unsigned long long s  = f2_add(f2_add(f2_mul(dx, dx), f2_mul(dy, dy)),
                                           f2_mul(dz, dz));
            float d2l, d2h;
            f2_unpack(s, d2l, d2h);
            float n0 = fminf(dd[2 * a + 0], d2l);
            float n1 = fminf(dd[2 * a + 1], d2h);
            dd[2 * a + 0] = n0;
            dd[2 * a + 1] = n1;
            if (n0 > m) { m = n0; mi = 2 * a + 0; }   // strict > keeps lowest idx on tie
            if (n1 > m) { m = n1; mi = 2 * a + 1; }
        }
        // key = (dist_bits << 32) | ~global_idx : max-reduce == argmax w/ lowest-idx tiebreak
        unsigned long long key =
            ((unsigned long long)__float_as_uint(m) << 32) |
            (unsigned)(~(unsigned)(base + mi));
#pragma unroll
        for (int off = 16; off; off >>= 1) {
            unsigned long long o = __shfl_down_sync(0xffffffffu, key, off);
            key = (o > key) ? o : key;
        }
        if (lane == 0) red[it & 1][wid] = key;
        __syncthreads();
        unsigned long long v = red[it & 1][lane];
#pragma unroll
        for (int off = 16; off; off >>= 1) {
            unsigned long long o = __shfl_xor_sync(0xffffffffu, v, off);
            v = (o > v) ? o : v;
        }
        const int idx = (int)(~(unsigned)v);
        const float x = spx[idx], y = spy[idx], z = spz[idx];   // broadcast LDS
        nlx = f2_pack(-x, -x);
        nly = f2_pack(-y, -y);
        nlz = f2_pack(-z, -z);
        if (t == 0) {
            g_new_idx[b * NPOINT + it] = idx;
            g_new_xyz[(size_t)(b * NPOINT + it) * 3 + 0] = x;
            g_new_xyz[(size_t)(b * NPOINT + it) * 3 + 1] = y;
            g_new_xyz[(size_t)(b * NPOINT + it) * 3 + 2] = z;
            out[OFF_IDX + b * NPOINT + it] = (float)idx;
            out[OFF_XYZ + (size_t)(b * NPOINT + it) * 3 + 0] = x;
            out[OFF_XYZ + (size_t)(b * NPOINT + it) * 3 + 1] = y;
            out[OFF_XYZ + (size_t)(b * NPOINT + it) * 3 + 2] = z;
        }
    }
}

// =============================================================================
// 2) Feature transpose [64, 65536] -> [65536, 64]
// =============================================================================
__global__ void transpose_kernel(const float* __restrict__ f) {
    __shared__ float tile[32][33];
    const int n0 = blockIdx.x * 32;
    const int c0 = blockIdx.y * 32;
    const int tx = threadIdx.x, ty = threadIdx.y;
#pragma unroll
    for (int i = 0; i < 4; i++)
        tile[ty + 8 * i][tx] = f[(size_t)(c0 + ty + 8 * i) * NTOT + (n0 + tx)];
    __syncthreads();
#pragma unroll
    for (int i = 0; i < 4; i++)
        g_featT[(size_t)(n0 + ty + 8 * i) * CIN + (c0 + tx)] = tile[tx][ty + 8 * i];
}

// =============================================================================
// 3) Ball query: one warp per center (unchanged; passed exactly).
// =============================================================================
__global__ void __launch_bounds__(256) ballq_kernel(const float* __restrict__ xyz,
                                                    float* __restrict__ out) {
    float* spx = dyn_smem;
    float* spy = spx + NPTS;
    float* spz = spy + NPTS;
    __shared__ int sm_ids[8][NSAMPLE];

    const int b = blockIdx.x >> 6;
    const int cblk = blockIdx.x & 63;
    const float* src = xyz + (size_t)b * NPTS * 3;

    for (int i = threadIdx.x; i < NPTS; i += 256) {
        spx[i] = src[3 * i + 0];
        spy[i] = src[3 * i + 1];
        spz[i] = src[3 * i + 2];
    }
    __syncthreads();

    const int w = threadIdx.x >> 5, lane = threadIdx.x & 31;
    const int gc = b * NPOINT + cblk * 8 + w;
    const float cx = g_new_xyz[(size_t)gc * 3 + 0];
    const float cy = g_new_xyz[(size_t)gc * 3 + 1];
    const float cz = g_new_xyz[(size_t)gc * 3 + 2];

    int count = 0, first = -1;
    for (int chunk = 0; chunk < NPTS / 32; ++chunk) {
        const int p = chunk * 32 + lane;
        float dx = __fsub_rn(cx, spx[p]);
        float dy = __fsub_rn(cy, spy[p]);
        float dz = __fsub_rn(cz, spz[p]);
        float d2 = __fadd_rn(__fadd_rn(__fmul_rn(dx, dx), __fmul_rn(dy, dy)),
                             __fmul_rn(dz, dz));
        const bool in = d2 < R2;
        const unsigned m = __ballot_sync(0xffffffffu, in);
        if (m) {
            if (first < 0) first = chunk * 32 + __ffs(m) - 1;
            if (in) {
                int rank = count + __popc(m & ((1u << lane) - 1u));
                if (rank < NSAMPLE) sm_ids[w][rank] = p;
            }
            count += __popc(m);
            if (count >= NSAMPLE) break;
        }
    }
    __syncwarp();
    if (first < 0) first = 0;
    const int id = (lane < count) ? sm_ids[w][lane] : first;
    g_sample_ids[(size_t)gc * NSAMPLE + lane] = id;
    out[OFF_SIDS + (size_t)gc * NSAMPLE + lane] = (float)id;
}

// =============================================================================
// 4) Fused gather + MLP(67->64->64->128, ReLU each) + max over samples.
//    One block = 8 centers = 256 sample columns. Register-tiled 8x8 GEMMs
//    with software-pipelined (double-buffered) shared-memory loads.
// =============================================================================
__device__ __forceinline__ void fma_tile(float acc[8][8],
                                         const float4& a0, const float4& a1,
                                         const float4& b0, const float4& b1) {
    const float a[8] = {a0.x, a0.y, a0.z, a0.w, a1.x, a1.y, a1.z, a1.w};
    const float bb[8] = {b0.x, b0.y, b0.z, b0.w, b1.x, b1.y, b1.z, b1.w};
#pragma unroll
    for (int i = 0; i < 8; i++)
#pragma unroll
        for (int j = 0; j < 8; j++) acc[i][j] += a[i] * bb[j];
}

template <int K, int LDA>
__device__ __forceinline__ void gemm8x8(const float* __restrict__ A,
                                        const float* __restrict__ Bm,
                                        int o0, int s0, float acc[8][8]) {
#pragma unroll
    for (int i = 0; i < 8; i++)
#pragma unroll
        for (int j = 0; j < 8; j++) acc[i][j] = 0.0f;

    float4 a0 = *(const float4*)&A[o0];
    float4 a1 = *(const float4*)&A[o0 + 4];
    float4 b0 = *(const float4*)&Bm[s0];
    float4 b1 = *(const float4*)&Bm[s0 + 4];
#pragma unroll 4
    for (int k = 0; k < K - 1; k++) {
        // prefetch k+1 before issuing k's FMAs
        float4 na0 = *(const float4*)&A[(k + 1) * LDA + o0];
        float4 na1 = *(const float4*)&A[(k + 1) * LDA + o0 + 4];
        float4 nb0 = *(const float4*)&Bm[(k + 1) * 256 + s0];
        float4 nb1 = *(const float4*)&Bm[(k + 1) * 256 + s0 + 4];
        fma_tile(acc, a0, a1, b0, b1);
        a0 = na0; a1 = na1; b0 = nb0; b1 = nb1;
    }
    fma_tile(acc, a0, a1, b0, b1);
}

__global__ void __launch_bounds__(256) mlp_kernel(const float* __restrict__ xyz,
                                                  const float* __restrict__ W0,
                                                  const float* __restrict__ b0,
                                                  const float* __restrict__ W1,
                                                  const float* __restrict__ b1,
                                                  const float* __restrict__ W2,
                                                  const float* __restrict__ b2,
                                                  float* __restrict__ out) {
    float* sW0 = dyn_smem;          // [67][64]  (k-major)
    float* sb0 = sW0 + 67 * 64;
    float* sW1 = sb0 + 64;          // [64][64]
    float* sb1 = sW1 + 64 * 64;
    float* sW2 = sb1 + 64;          // [64][128]
    float* sb2 = sW2 + 64 * 128;
    float* X0  = sb2 + 128;         // [67][256]  (also reused as H2 [64][256])
    float* H1  = X0 + 67 * 256;     // [64][256]

    const int tid = threadIdx.x;
    const int b = blockIdx.x >> 6;
    const int cgrp = blockIdx.x & 63;

    // stage weights (transposed to k-major) + biases
    for (int i = tid; i < 67 * 64; i += 256) { int k = i >> 6, o = i & 63;  sW0[i] = W0[o * 67 + k]; }
    for (int i = tid; i < 64 * 64; i += 256) { int k = i >> 6, o = i & 63;  sW1[i] = W1[o * 64 + k]; }
    for (int i = tid; i < 64 * 128; i += 256){ int k = i >> 7, o = i & 127; sW2[i] = W2[o * 64 + k]; }
    if (tid < 64)  { sb0[tid] = b0[tid]; sb1[tid] = b1[tid]; }
    if (tid < 128) { sb2[tid] = b2[tid]; }

    // gather: each thread owns one sample column
    {
        const int s = tid;
        const int cl = s >> 5;
        const int gc = b * NPOINT + cgrp * 8 + cl;
        const int pid = g_sample_ids[(size_t)gc * NSAMPLE + (s & 31)];
        const float* p = xyz + ((size_t)b * NPTS + pid) * 3;
        const float cx = g_new_xyz[(size_t)gc * 3 + 0];
        const float cy = g_new_xyz[(size_t)gc * 3 + 1];
        const float cz = g_new_xyz[(size_t)gc * 3 + 2];
        X0[0 * 256 + s] = p[0] - cx;
        X0[1 * 256 + s] = p[1] - cy;
        X0[2 * 256 + s] = p[2] - cz;
        const float4* fp = (const float4*)(g_featT + ((size_t)b * NPTS + pid) * CIN);
#pragma unroll
        for (int q = 0; q < 16; q++) {
            float4 v = fp[q];
            X0[(3 + 4 * q + 0) * 256 + s] = v.x;
            X0[(3 + 4 * q + 1) * 256 + s] = v.y;
            X0[(3 + 4 * q + 2) * 256 + s] = v.z;
            X0[(3 + 4 * q + 3) * 256 + s] = v.w;
        }
    }
    __syncthreads();

    const int ot = tid >> 5, st = tid & 31;
    const int o0 = ot * 8, s0 = st * 8;
    float acc[8][8];

    // layer 1: 67 -> 64
    gemm8x8<67, 64>(sW0, X0, o0, s0, acc);
#pragma unroll
    for (int i = 0; i < 8; i++) {
        const float bi = sb0[o0 + i];
        float* dst = &H1[(o0 + i) * 256 + s0];
#pragma unroll
        for (int j = 0; j < 8; j++) dst[j] = fmaxf(acc[i][j] + bi, 0.0f);
    }
    __syncthreads();

    // layer 2: 64 -> 64  (write H2 into X0 buffer)
    gemm8x8<64, 64>(sW1, H1, o0, s0, acc);
#pragma unroll
    for (int i = 0; i < 8; i++) {
        const float bi = sb1[o0 + i];
        float* dst = &X0[(o0 + i) * 256 + s0];
#pragma unroll
        for (int j = 0; j < 8; j++) dst[j] = fmaxf(acc[i][j] + bi, 0.0f);
    }
    __syncthreads();

    // layer 3: 64 -> 128 in two halves, max-over-samples fused in epilogue
#pragma unroll
    for (int half = 0; half < 2; ++half) {
        gemm8x8<64, 128>(sW2 + half * 64, X0, o0, s0, acc);
#pragma unroll
        for (int i = 0; i < 8; i++) {
            const float bi = sb2[half * 64 + o0 + i];
            float m = 0.0f;  // ReLU outputs are >= 0
#pragma unroll
            for (int j = 0; j < 8; j++) m = fmaxf(m, fmaxf(acc[i][j] + bi, 0.0f));
            m = fmaxf(m, __shfl_xor_sync(0xffffffffu, m, 1));
            m = fmaxf(m, __shfl_xor_sync(0xffffffffu, m, 2));
            if ((st & 3) == 0) {
                const int c = cgrp * 8 + (st >> 2);
                const int o = half * 64 + o0 + i;
                out[OFF_FEAT + ((size_t)b * 128 + o) * NPOINT + c] = m;
            }
        }
    }
}

// =============================================================================
extern "C" void kernel_launch(void* const* d_in, const int* in_sizes, int n_in,
                              void* d_out, int out_size) {
    const float* xyz  = (const float*)d_in[0];
    const float* feat = (const float*)d_in[1];
    const float* W0   = (const float*)d_in[3];
    const float* b0   = (const float*)d_in[4];
    const float* W1   = (const float*)d_in[5];
    const float* b1   = (const float*)d_in[6];
    const float* W2   = (const float*)d_in[7];
    const float* b2   = (const float*)d_in[8];
    float* out = (float*)d_out;

    const int smem_pts = 3 * NPTS * sizeof(float);                 // 98304
    const int smem_mlp = (67*64 + 64 + 64*64 + 64 + 64*128 + 128
                          + 67*256 + 64*256) * sizeof(float);      // 201472

    cudaFuncSetAttribute(fps_kernel,   cudaFuncAttributeMaxDynamicSharedMemorySize, smem_pts);
    cudaFuncSetAttribute(ballq_kernel, cudaFuncAttributeMaxDynamicSharedMemorySize, smem_pts);
    cudaFuncSetAttribute(mlp_kernel,   cudaFuncAttributeMaxDynamicSharedMemorySize, smem_mlp);

    fps_kernel<<<BATCH, 1024, smem_pts>>>(xyz, out);
    transpose_kernel<<<dim3(NTOT / 32, CIN / 32), dim3(32, 8)>>>(feat);
    ballq_kernel<<<BATCH * (NPOINT / 8), 256, smem_pts>>>(xyz, out);
    mlp_kernel<<<BATCH * (NPOINT / 8), 256, smem_mlp>>>(xyz, W0, b0, W1, b1, W2, b2, out);
}